// round 1
// baseline (speedup 1.0000x reference)
#include <cuda_runtime.h>
#include <math.h>

// Problem constants (fixed by reference setup)
#define Bsz 2
#define Dm  128
#define Nn  2048
#define Hh  4
#define DH  32

// ---------------- scratch (device globals; no allocation) ----------------
__device__ float g_x0[Bsz*Dm*Nn];
__device__ float g_x1[Bsz*Dm*Nn];
__device__ float g_s0[Bsz*Dm*Nn];
__device__ float g_s1[Bsz*Dm*Nn];
__device__ float g_q [Bsz*Dm*Nn];
__device__ float g_k [Bsz*Dm*Nn];
__device__ float g_v [Bsz*Dm*Nn];
__device__ float g_prob[(size_t)Bsz*Hh*Nn*Nn];   // 134 MB, layer-0 worst case
__device__ float g_msg[Bsz*Dm*Nn];
__device__ float g_y [Bsz*2*Dm*Nn];
__device__ float g_h [Bsz*2*Dm*Nn];
__device__ float g_p0[Bsz*Nn];
__device__ float g_p1[Bsz*Nn];
__device__ int   g_idx0[Bsz*Nn];
__device__ int   g_idx1[Bsz*Nn];

// ---------------- tiny utility kernels ----------------
__global__ void copyf_kernel(const float* __restrict__ src, float* __restrict__ dst, int n)
{
    int g = blockIdx.x*256 + threadIdx.x;
    if (g < n) dst[g] = src[g];
}

__global__ void zero_kernel(float* __restrict__ p, int n)
{
    int g = blockIdx.x*256 + threadIdx.x;
    if (g < n) p[g] = 0.0f;
}

__global__ void iota_kernel(int* __restrict__ idx)
{
    int g = blockIdx.x*256 + threadIdx.x;   // over Bsz*Nn
    if (g < Bsz*Nn) idx[g] = g % Nn;
}

__global__ void out_kernel(const float* __restrict__ x0, const float* __restrict__ x1,
                           float* __restrict__ out)
{
    int g = blockIdx.x*256 + threadIdx.x;   // over Bsz*Dm*Nn
    if (g < Bsz*Dm*Nn) {
        out[g] = x0[g];
        out[g + Bsz*Dm*Nn] = x1[g];
    }
}

// copy x into first 128 channels of y ([B,256,N])
__global__ void copy_xy_kernel(const float* __restrict__ x, float* __restrict__ y)
{
    int g = blockIdx.x*256 + threadIdx.x;   // over Bsz*Dm*Nn
    if (g >= Bsz*Dm*Nn) return;
    int b = g / (Dm*Nn);
    int r = g - b*(Dm*Nn);
    y[(size_t)b*2*Dm*Nn + r] = x[g];
}

// ---------------- gather: s[b,d,k] = x[b,d,idx[b,k]] ----------------
__global__ void gather_kernel(const float* __restrict__ x, const int* __restrict__ idx,
                              float* __restrict__ s, int K)
{
    int g = blockIdx.x*256 + threadIdx.x;
    int total = Bsz*Dm*K;
    if (g >= total) return;
    int b = g / (Dm*K);
    int r = g - b*(Dm*K);
    int d = r / K, kk = r - d*K;
    s[g] = x[(size_t)b*Dm*Nn + (size_t)d*Nn + idx[b*Nn + kk]];
}

// ---------------- pointwise conv GEMM: Y[b,o,n] = sum_i W[o,i] X[b,i,n] + bias[o] ----------------
// grid: (Ncols/64, Co/64, B), block 256. BM=BN=64, BK=16, 4x4 microtile.
__global__ void pw_gemm_kernel(const float* __restrict__ W, const float* __restrict__ bias,
                               const float* __restrict__ X, int xbStride,
                               float* __restrict__ Y, int ybStride,
                               int Ci, int Ncols, int accumulate)
{
    __shared__ float Ws[64][17];
    __shared__ float Xs[16][64];
    int b = blockIdx.z;
    const float* Xb = X + (size_t)b * xbStride;
    float*       Yb = Y + (size_t)b * ybStride;
    int coTile  = blockIdx.y * 64;
    int colTile = blockIdx.x * 64;
    int tid = threadIdx.x;
    int ty = tid >> 4, tx = tid & 15;
    float acc[4][4] = {};

    for (int kt = 0; kt < Ci; kt += 16) {
        #pragma unroll
        for (int q = 0; q < 4; q++) {
            int e = tid + 256*q;
            int r = e >> 4, c = e & 15;
            Ws[r][c] = W[(size_t)(coTile + r)*Ci + kt + c];
        }
        #pragma unroll
        for (int q = 0; q < 4; q++) {
            int e = tid + 256*q;
            int r = e >> 6, c = e & 63;
            Xs[r][c] = Xb[(size_t)(kt + r)*Ncols + colTile + c];
        }
        __syncthreads();
        #pragma unroll
        for (int kk = 0; kk < 16; kk++) {
            float a[4], bb[4];
            #pragma unroll
            for (int i = 0; i < 4; i++) a[i]  = Ws[ty*4+i][kk];
            #pragma unroll
            for (int j = 0; j < 4; j++) bb[j] = Xs[kk][tx*4+j];
            #pragma unroll
            for (int i = 0; i < 4; i++)
                #pragma unroll
                for (int j = 0; j < 4; j++)
                    acc[i][j] += a[i]*bb[j];
        }
        __syncthreads();
    }

    #pragma unroll
    for (int i = 0; i < 4; i++) {
        int row = coTile + ty*4 + i;
        float bi = bias[row];
        #pragma unroll
        for (int j = 0; j < 4; j++) {
            int col = colTile + tx*4 + j;
            size_t off = (size_t)row*Ncols + col;
            float val = acc[i][j] + bi;
            Yb[off] = accumulate ? (Yb[off] + val) : val;
        }
    }
}

// ---------------- scores: prob[b,h,n,k] = scale * sum_i q[b,i*4+h,n]*kb[b,i*4+h,k] ----------------
// grid: (K/64, N/64, B*H), block 256
__global__ void scores_kernel(const float* __restrict__ q, const float* __restrict__ kbuf,
                              float* __restrict__ prob, int K)
{
    __shared__ float Qs[32][64];
    __shared__ float Ks[32][64];
    int z = blockIdx.z; int b = z >> 2; int h = z & 3;
    int nTile = blockIdx.y * 64;
    int kTile = blockIdx.x * 64;
    int tid = threadIdx.x; int ty = tid >> 4, tx = tid & 15;
    const float* qb = q    + (size_t)b*Dm*Nn;
    const float* kb = kbuf + (size_t)b*Dm*K;

    #pragma unroll
    for (int qq = 0; qq < 8; qq++) {
        int e = tid + 256*qq;
        int i = e >> 6, c = e & 63;
        Qs[i][c] = qb[(size_t)(i*4 + h)*Nn + nTile + c];
        Ks[i][c] = kb[(size_t)(i*4 + h)*K  + kTile + c];
    }
    __syncthreads();

    float acc[4][4] = {};
    #pragma unroll
    for (int i = 0; i < 32; i++) {
        float a[4], c4[4];
        #pragma unroll
        for (int r = 0; r < 4; r++) a[r]  = Qs[i][ty*4+r];
        #pragma unroll
        for (int j = 0; j < 4; j++) c4[j] = Ks[i][tx*4+j];
        #pragma unroll
        for (int r = 0; r < 4; r++)
            #pragma unroll
            for (int j = 0; j < 4; j++)
                acc[r][j] += a[r]*c4[j];
    }

    const float scale = 0.17677669529663687f;   // 1/sqrt(32)
    float* pr = prob + (size_t)z*Nn*K;
    #pragma unroll
    for (int r = 0; r < 4; r++)
        #pragma unroll
        for (int j = 0; j < 4; j++)
            pr[(size_t)(nTile + ty*4 + r)*K + kTile + tx*4 + j] = acc[r][j]*scale;
}

// ---------------- softmax over K (one block per row; K in {256,512,1024,2048}) ----------------
__global__ void softmax_kernel(float* __restrict__ prob, int K)
{
    float* p = prob + (size_t)blockIdx.x * K;
    int tid = threadIdx.x;
    int cnt = K >> 8;
    float v[8];
    float m = -1e30f;
    for (int j = 0; j < cnt; j++) { v[j] = p[tid + j*256]; m = fmaxf(m, v[j]); }
    __shared__ float red[256];
    red[tid] = m; __syncthreads();
    for (int s = 128; s > 0; s >>= 1) { if (tid < s) red[tid] = fmaxf(red[tid], red[tid+s]); __syncthreads(); }
    m = red[0]; __syncthreads();
    float sum = 0.0f;
    for (int j = 0; j < cnt; j++) { v[j] = expf(v[j] - m); sum += v[j]; }
    red[tid] = sum; __syncthreads();
    for (int s = 128; s > 0; s >>= 1) { if (tid < s) red[tid] += red[tid+s]; __syncthreads(); }
    float inv = 1.0f / red[0];
    for (int j = 0; j < cnt; j++) p[tid + j*256] = v[j]*inv;
}

// ---------------- key importance: p[b,k] = (1/H) sum_{h,n} prob[b,h,n,k] ----------------
// grid: ((B*K+255)/256, Nn/128), block 256; pout must be zeroed first.
__global__ void pred_kernel(const float* __restrict__ prob, float* __restrict__ pout, int K)
{
    int g = blockIdx.x*256 + threadIdx.x;
    if (g >= Bsz*K) return;
    int b = g / K, k = g - b*K;
    int n0 = blockIdx.y * 128;
    const float* base = prob + (size_t)b*Hh*Nn*K + k;
    float s = 0.0f;
    for (int h = 0; h < Hh; h++) {
        const float* ph = base + ((size_t)h*Nn + n0)*K;
        #pragma unroll 4
        for (int n = 0; n < 128; n++) s += ph[(size_t)n*K];
    }
    atomicAdd(&pout[g], s * 0.25f);
}

// ---------------- msg: msg[b,i*4+h,n] = sum_k prob[b,h,n,k]*v[b,i*4+h,k] ----------------
// grid: (N/64, B*H), block 256
__global__ void msg_kernel(const float* __restrict__ prob, const float* __restrict__ v,
                           float* __restrict__ msg, int K)
{
    __shared__ float Vs[32][65];
    __shared__ float Ps[64][65];
    int z = blockIdx.y; int b = z >> 2, h = z & 3;
    int nTile = blockIdx.x * 64;
    int tid = threadIdx.x;
    const float* vb = v    + (size_t)b*Dm*K;
    const float* pr = prob + (size_t)z*Nn*K;
    int i = tid & 31, ng = tid >> 5;
    float acc[8] = {};

    for (int kt = 0; kt < K; kt += 64) {
        #pragma unroll
        for (int qq = 0; qq < 8; qq++) {
            int e = tid + 256*qq;
            int r = e >> 6, c = e & 63;
            Vs[r][c] = vb[(size_t)(r*4 + h)*K + kt + c];
        }
        #pragma unroll
        for (int qq = 0; qq < 16; qq++) {
            int e = tid + 256*qq;
            int r = e >> 6, c = e & 63;
            Ps[r][c] = pr[(size_t)(nTile + r)*K + kt + c];
        }
        __syncthreads();
        #pragma unroll
        for (int kk = 0; kk < 64; kk++) {
            float vv = Vs[i][kk];
            #pragma unroll
            for (int j = 0; j < 8; j++) acc[j] += vv * Ps[ng*8 + j][kk];
        }
        __syncthreads();
    }

    float* mb = msg + (size_t)b*Dm*Nn + (size_t)(i*4 + h)*Nn + nTile + ng*8;
    #pragma unroll
    for (int j = 0; j < 8; j++) mb[j] = acc[j];
}

// ---------------- instance norm (eps=1e-3) + relu, in place; one block per (b,c) row ----------------
__global__ void instnorm_relu_kernel(float* __restrict__ x)
{
    float* p = x + (size_t)blockIdx.x * Nn;
    int tid = threadIdx.x;
    float v[8];
    float s = 0.0f;
    #pragma unroll
    for (int j = 0; j < 8; j++) { v[j] = p[tid + j*256]; s += v[j]; }
    __shared__ float red[256];
    red[tid] = s; __syncthreads();
    for (int st = 128; st > 0; st >>= 1) { if (tid < st) red[tid] += red[tid+st]; __syncthreads(); }
    float mean = red[0] * (1.0f/Nn);
    __syncthreads();
    float s2 = 0.0f;
    #pragma unroll
    for (int j = 0; j < 8; j++) { float d = v[j] - mean; s2 += d*d; }
    red[tid] = s2; __syncthreads();
    for (int st = 128; st > 0; st >>= 1) { if (tid < st) red[tid] += red[tid+st]; __syncthreads(); }
    float rs = rsqrtf(red[0]*(1.0f/Nn) + 1e-3f);
    #pragma unroll
    for (int j = 0; j < 8; j++) {
        float o = (v[j] - mean)*rs;
        p[tid + j*256] = o > 0.0f ? o : 0.0f;
    }
}

// ---------------- pooling: exact top-k (jax.lax.top_k tie-break) + sorted gather ----------------
// one block per batch; idx updated in place (values staged in shared first)
__global__ void pool_kernel(const float* __restrict__ p, int* __restrict__ idx, int K, int kkeep)
{
    __shared__ float sp[2048];
    __shared__ int   sidx[2048];
    __shared__ int   sflag[2048];
    int b = blockIdx.x;
    int tid = threadIdx.x;
    for (int j = tid; j < K; j += 256) { sp[j] = p[b*K + j]; sidx[j] = idx[b*Nn + j]; }
    __syncthreads();
    for (int pos = tid; pos < K; pos += 256) {
        float v = sp[pos];
        int r = 0;
        for (int j = 0; j < K; j++) {
            float u = sp[j];
            r += (u > v) || (u == v && j < pos);
        }
        sflag[pos] = (r < kkeep) ? 1 : 0;
    }
    __syncthreads();
    for (int pos = tid; pos < K; pos += 256) {
        if (sflag[pos]) {
            int o = 0;
            for (int j = 0; j < pos; j++) o += sflag[j];
            idx[b*Nn + o] = sidx[pos];
        }
    }
}

// ---------------- host-side pipeline ----------------
static void attn_prop(float* x, const float* s, int l, int K, float* pimp,
                      const float* Wq, const float* bq, const float* Wk, const float* bk,
                      const float* Wv, const float* bv, const float* Wm, const float* bm,
                      const float* W1, const float* b1, const float* W2, const float* b2,
                      float* q, float* k, float* v, float* prob, float* msg, float* y, float* h)
{
    // q/k/v projections
    pw_gemm_kernel<<<dim3(Nn/64, Dm/64, Bsz), 256>>>(Wq + (size_t)l*Dm*Dm, bq + l*Dm,
                                                     x, Dm*Nn, q, Dm*Nn, Dm, Nn, 0);
    pw_gemm_kernel<<<dim3(K/64,  Dm/64, Bsz), 256>>>(Wk + (size_t)l*Dm*Dm, bk + l*Dm,
                                                     s, Dm*K, k, Dm*K, Dm, K, 0);
    pw_gemm_kernel<<<dim3(K/64,  Dm/64, Bsz), 256>>>(Wv + (size_t)l*Dm*Dm, bv + l*Dm,
                                                     s, Dm*K, v, Dm*K, Dm, K, 0);
    // attention
    scores_kernel<<<dim3(K/64, Nn/64, Bsz*Hh), 256>>>(q, k, prob, K);
    softmax_kernel<<<Bsz*Hh*Nn, 256>>>(prob, K);
    zero_kernel<<<(Bsz*K + 255)/256, 256>>>(pimp, Bsz*K);
    pred_kernel<<<dim3((Bsz*K + 255)/256, Nn/128), 256>>>(prob, pimp, K);
    msg_kernel<<<dim3(Nn/64, Bsz*Hh), 256>>>(prob, v, msg, K);
    // concat + message projection into y
    copy_xy_kernel<<<(Bsz*Dm*Nn)/256, 256>>>(x, y);
    pw_gemm_kernel<<<dim3(Nn/64, Dm/64, Bsz), 256>>>(Wm + (size_t)l*Dm*Dm, bm + l*Dm,
                                                     msg, Dm*Nn, y + Dm*Nn, 2*Dm*Nn, Dm, Nn, 0);
    // MLP: h = relu(instnorm(W1 y + b1)); x += W2 h + b2
    pw_gemm_kernel<<<dim3(Nn/64, (2*Dm)/64, Bsz), 256>>>(W1 + (size_t)l*2*Dm*2*Dm, b1 + l*2*Dm,
                                                         y, 2*Dm*Nn, h, 2*Dm*Nn, 2*Dm, Nn, 0);
    instnorm_relu_kernel<<<Bsz*2*Dm, 256>>>(h);
    pw_gemm_kernel<<<dim3(Nn/64, Dm/64, Bsz), 256>>>(W2 + (size_t)l*Dm*2*Dm, b2 + l*Dm,
                                                     h, 2*Dm*Nn, x, Dm*Nn, 2*Dm, Nn, 1);
}

extern "C" void kernel_launch(void* const* d_in, const int* in_sizes, int n_in,
                              void* d_out, int out_size)
{
    const float* x0in = (const float*)d_in[0];
    const float* x1in = (const float*)d_in[1];
    const float* Wq = (const float*)d_in[2];
    const float* bq = (const float*)d_in[3];
    const float* Wk = (const float*)d_in[4];
    const float* bk = (const float*)d_in[5];
    const float* Wv = (const float*)d_in[6];
    const float* bv = (const float*)d_in[7];
    const float* Wm = (const float*)d_in[8];
    const float* bm = (const float*)d_in[9];
    const float* W1 = (const float*)d_in[10];
    const float* b1 = (const float*)d_in[11];
    const float* W2 = (const float*)d_in[12];
    const float* b2 = (const float*)d_in[13];
    float* out = (float*)d_out;

    float *x0, *x1, *s0, *s1, *q, *k, *v, *prob, *msg, *y, *h, *p0, *p1;
    int *idx0, *idx1;
    cudaGetSymbolAddress((void**)&x0, g_x0);
    cudaGetSymbolAddress((void**)&x1, g_x1);
    cudaGetSymbolAddress((void**)&s0, g_s0);
    cudaGetSymbolAddress((void**)&s1, g_s1);
    cudaGetSymbolAddress((void**)&q,  g_q);
    cudaGetSymbolAddress((void**)&k,  g_k);
    cudaGetSymbolAddress((void**)&v,  g_v);
    cudaGetSymbolAddress((void**)&prob, g_prob);
    cudaGetSymbolAddress((void**)&msg,  g_msg);
    cudaGetSymbolAddress((void**)&y,    g_y);
    cudaGetSymbolAddress((void**)&h,    g_h);
    cudaGetSymbolAddress((void**)&p0,   g_p0);
    cudaGetSymbolAddress((void**)&p1,   g_p1);
    cudaGetSymbolAddress((void**)&idx0, g_idx0);
    cudaGetSymbolAddress((void**)&idx1, g_idx1);

    const int total = Bsz*Dm*Nn;
    copyf_kernel<<<total/256, 256>>>(x0in, x0, total);
    copyf_kernel<<<total/256, 256>>>(x1in, x1, total);
    iota_kernel<<<(Bsz*Nn)/256, 256>>>(idx0);
    iota_kernel<<<(Bsz*Nn)/256, 256>>>(idx1);

    const int Ks[4] = {2048, 1024, 512, 256};
    for (int l = 0; l < 4; l++) {
        int K = Ks[l];
        int cross = (l & 1);
        const float* gx0 = cross ? x1 : x0;
        const int*   gi0 = cross ? idx1 : idx0;
        const float* gx1 = cross ? x0 : x1;
        const int*   gi1 = cross ? idx0 : idx1;
        int gth = (Bsz*Dm*K + 255)/256;
        gather_kernel<<<gth, 256>>>(gx0, gi0, s0, K);
        gather_kernel<<<gth, 256>>>(gx1, gi1, s1, K);

        attn_prop(x0, s0, l, K, p0, Wq, bq, Wk, bk, Wv, bv, Wm, bm, W1, b1, W2, b2,
                  q, k, v, prob, msg, y, h);
        attn_prop(x1, s1, l, K, p1, Wq, bq, Wk, bk, Wv, bv, Wm, bm, W1, b1, W2, b2,
                  q, k, v, prob, msg, y, h);

        if (l < 3) {
            int kkeep = K/2;   // always >= MIN_NGHS for this schedule
            if (!cross) {
                pool_kernel<<<Bsz, 256>>>(p0, idx0, K, kkeep);
                pool_kernel<<<Bsz, 256>>>(p1, idx1, K, kkeep);
            } else {
                pool_kernel<<<Bsz, 256>>>(p0, idx1, K, kkeep);
                pool_kernel<<<Bsz, 256>>>(p1, idx0, K, kkeep);
            }
        }
    }

    out_kernel<<<total/256, 256>>>(x0, x1, out);
}